// round 9
// baseline (speedup 1.0000x reference)
#include <cuda_runtime.h>
#include <cuda_bf16.h>
#include <math.h>

// Problem constants (fixed by the dataset)
#define NN   20000     // nodes
#define NE   100000    // edges (without self loops)
#define NR   1000      // relations
#define NF   128       // feature dim
#define NH   4         // heads
#define NL   4         // layers
#define HC   512       // NH*NF
#define ETOT (NE + NN) // edges incl self loops = 120000

// ---------------- scratch (static device globals; no runtime allocation) ----
__device__ float g_XL[(size_t)NN * HC];        // 41 MB  source projection
__device__ float g_XR[(size_t)NN * HC];        // 41 MB  target projection
__device__ float g_REL[(size_t)(NR + 1) * HC]; // 2 MB   edge embeddings (row NR = mean)
__device__ float g_relext[(size_t)(NR + 1) * NF]; // relations + mean row
__device__ float g_H[2 * (size_t)NN * NF];     // ping-pong node features
__device__ float g_part[125][NF];              // eamean partials
__device__ int   g_cnt[NN];
__device__ int   g_rcnt[NR];
__device__ int   g_rowptr[NN + 1];
__device__ int   g_offs[NN];
__device__ int   g_esrc[ETOT];
__device__ int   g_erel[ETOT];

// ---------------- preprocessing kernels -------------------------------------
// merged: reset histograms + copy relations into relext and output region
__global__ void k_init(const float* __restrict__ relations,
                       float* __restrict__ out, int out_size) {
    int i = blockIdx.x * blockDim.x + threadIdx.x;
    if (i < NN) g_cnt[i] = 1;              // self loop pre-counted
    if (i < NR) g_rcnt[i] = 0;
    if (i < NR * NF) {
        float v = relations[i];
        g_relext[i] = v;
        if (out_size >= NN * NF + NR * NF) out[NN * NF + i] = v;
    }
}

__global__ void k_hist(const int* __restrict__ ei, const int* __restrict__ relidx) {
    int e = blockIdx.x * blockDim.x + threadIdx.x;
    if (e < NE) {
        atomicAdd(&g_cnt[ei[NE + e]], 1);  // dst row
        atomicAdd(&g_rcnt[relidx[e]], 1);
    }
}

// single-block scan over 20000 counts -> rowptr + offs
__global__ void k_scan() {
    __shared__ int s[1024];
    int t = threadIdx.x;
    const int CH = 20;                      // 1024*20 >= 20000
    int beg = t * CH, end = min(beg + CH, NN);
    int sum = 0;
    for (int i = beg; i < end; i++) sum += g_cnt[i];
    s[t] = sum;
    __syncthreads();
    for (int off = 1; off < 1024; off <<= 1) {
        int v = (t >= off) ? s[t - off] : 0;
        __syncthreads();
        s[t] += v;
        __syncthreads();
    }
    int base = (t == 0) ? 0 : s[t - 1];
    for (int i = beg; i < end; i++) {
        g_rowptr[i] = base;
        g_offs[i]   = base;
        base += g_cnt[i];
    }
    if (t == 1023) g_rowptr[NN] = s[1023];
}

// eamean stage 1: 125 blocks x 128 threads, 8 relations each
__global__ void k_eamean1(const float* __restrict__ relations) {
    int b = blockIdx.x, f = threadIdx.x;
    float s = 0.0f;
#pragma unroll
    for (int j = 0; j < 8; j++) {
        int r = b * 8 + j;
        s += (float)g_rcnt[r] * __ldg(relations + (size_t)r * NF + f);
    }
    g_part[b][f] = s;
}

// eamean stage 2: combine 125 partials (deterministic)
__global__ void k_eamean2() {
    int f = threadIdx.x;
    float s = 0.0f;
#pragma unroll 5
    for (int b = 0; b < 125; b++) s += g_part[b][f];
    g_relext[(size_t)NR * NF + f] = s * (1.0f / NE);
}

// merged: scatter edges + self loops (counting-sort by dst)
__global__ void k_scatter(const int* __restrict__ ei, const int* __restrict__ relidx) {
    int e = blockIdx.x * blockDim.x + threadIdx.x;
    if (e < NE) {
        int s = ei[e], d = ei[NE + e];
        int pos = atomicAdd(&g_offs[d], 1);
        g_esrc[pos] = s;
        g_erel[pos] = relidx[e];
    } else if (e < NE + NN) {
        int n = e - NE;
        int pos = atomicAdd(&g_offs[n], 1);
        g_esrc[pos] = n;
        g_erel[pos] = NR;                   // mean-attr row
    }
}

// ---------------- tf32 tensor-core GEMM -------------------------------------
// One launch per layer: blockIdx.z selects {XL, XR, REL} problem.
// tf32 conversion at SMEM-store; double-buffered K-chunk pipeline.
// __launch_bounds__(256, 2): cap regs at 128 so 2 CTAs/SM co-reside.
__device__ __forceinline__ unsigned f2tf(float x) {
    unsigned r;
    asm("cvt.rna.tf32.f32 %0, %1;" : "=r"(r) : "f"(x));
    return r;
}

__device__ __forceinline__ void mma_tf32(float* c, const unsigned* a,
                                         unsigned b0, unsigned b1) {
    asm("mma.sync.aligned.m16n8k8.row.col.f32.tf32.tf32.f32 "
        "{%0,%1,%2,%3},{%4,%5,%6,%7},{%8,%9},{%0,%1,%2,%3};"
        : "+f"(c[0]), "+f"(c[1]), "+f"(c[2]), "+f"(c[3])
        : "r"(a[0]), "r"(a[1]), "r"(a[2]), "r"(a[3]), "r"(b0), "r"(b1));
}

#define AS_STRIDE 36                 // banks (4g+tg) distinct mod 32
#define BS_STRIDE 136                // banks (8tg+g) distinct mod 32
#define ASZ (128 * AS_STRIDE)        // u32 per A buffer
#define BSZ (32 * BS_STRIDE)         // u32 per B buffer
#define GEMM_SMEM_BYTES (2 * (ASZ + BSZ) * 4)   // 71680

__global__ void __launch_bounds__(256, 2)
gemm3_tf32(const float* __restrict__ Hin,
           const float* __restrict__ Wl, const float* __restrict__ bl,
           const float* __restrict__ Wr, const float* __restrict__ br,
           const float* __restrict__ We,
           float* __restrict__ XL, float* __restrict__ XR, float* __restrict__ REL) {
    const float* A; const float* B; const float* bias; float* C; int M;
    int z = blockIdx.z;
    if (z == 0)      { A = Hin;      B = Wl; bias = bl;      C = XL;  M = NN; }
    else if (z == 1) { A = Hin;      B = Wr; bias = br;      C = XR;  M = NN; }
    else             { A = g_relext; B = We; bias = nullptr; C = REL; M = NR + 1;
                       if (blockIdx.y * 128 >= NR + 1) return; }

    extern __shared__ unsigned smem[];
    unsigned* Abuf[2] = { smem, smem + ASZ };
    unsigned* Bbuf[2] = { smem + 2 * ASZ, smem + 2 * ASZ + BSZ };

    int t = threadIdx.x;
    int warp = t >> 5, lane = t & 31;
    int g = lane >> 2, tg = lane & 3;
    int m0 = blockIdx.y * 128, n0 = blockIdx.x * 128;
    int wm = (warp >> 1) * 32;
    int wn = (warp & 1) * 64;

    float4 ar[4], br4[4];

    auto ldA = [&](int kc) {
#pragma unroll
        for (int i = 0; i < 4; i++) {
            int flat = i * 256 + t;
            int row = flat >> 3, c4 = flat & 7;
            int gr = m0 + row;
            ar[i] = (gr < M)
                ? __ldg((const float4*)(A + (size_t)gr * NF + kc * 32) + c4)
                : make_float4(0.f, 0.f, 0.f, 0.f);
        }
    };
    auto ldB = [&](int kc) {
#pragma unroll
        for (int i = 0; i < 4; i++) {
            int flat = i * 256 + t;
            int kr = flat >> 5, c4 = flat & 31;
            br4[i] = __ldg((const float4*)(B + (size_t)(kc * 32 + kr) * HC + n0) + c4);
        }
    };
    auto stAB = [&](int buf) {
        unsigned* As = Abuf[buf];
        unsigned* Bs = Bbuf[buf];
#pragma unroll
        for (int i = 0; i < 4; i++) {
            int flat = i * 256 + t;
            int row = flat >> 3, c4 = flat & 7;
            uint4 v = make_uint4(f2tf(ar[i].x), f2tf(ar[i].y),
                                 f2tf(ar[i].z), f2tf(ar[i].w));
            *(uint4*)&As[row * AS_STRIDE + c4 * 4] = v;
        }
#pragma unroll
        for (int i = 0; i < 4; i++) {
            int flat = i * 256 + t;
            int kr = flat >> 5, c4 = flat & 31;
            uint4 v = make_uint4(f2tf(br4[i].x), f2tf(br4[i].y),
                                 f2tf(br4[i].z), f2tf(br4[i].w));
            *(uint4*)&Bs[kr * BS_STRIDE + c4 * 4] = v;
        }
    };

    float acc[2][8][4] = {};

    ldA(0); ldB(0);
    stAB(0);
    __syncthreads();

    for (int kc = 0; kc < 4; kc++) {
        if (kc < 3) { ldA(kc + 1); ldB(kc + 1); }   // prefetch

        const unsigned* As = Abuf[kc & 1];
        const unsigned* Bs = Bbuf[kc & 1];
#pragma unroll
        for (int ks = 0; ks < 4; ks++) {
            int k0 = ks * 8;
            unsigned a[2][4];
#pragma unroll
            for (int mf = 0; mf < 2; mf++) {
                int r = wm + mf * 16 + g;
                a[mf][0] = As[r * AS_STRIDE + k0 + tg];
                a[mf][1] = As[(r + 8) * AS_STRIDE + k0 + tg];
                a[mf][2] = As[r * AS_STRIDE + k0 + tg + 4];
                a[mf][3] = As[(r + 8) * AS_STRIDE + k0 + tg + 4];
            }
#pragma unroll
            for (int nf = 0; nf < 8; nf++) {
                int c = wn + nf * 8 + g;
                unsigned b0 = Bs[(k0 + tg) * BS_STRIDE + c];
                unsigned b1 = Bs[(k0 + tg + 4) * BS_STRIDE + c];
                mma_tf32(acc[0][nf], a[0], b0, b1);
                mma_tf32(acc[1][nf], a[1], b0, b1);
            }
        }
        if (kc < 3) {
            stAB((kc + 1) & 1);
            __syncthreads();
        }
    }

#pragma unroll
    for (int nf = 0; nf < 8; nf++) {
        int col = n0 + wn + nf * 8 + 2 * tg;
        float2 bi = make_float2(0.f, 0.f);
        if (bias) bi = *(const float2*)(bias + col);
#pragma unroll
        for (int mf = 0; mf < 2; mf++) {
            int row = m0 + wm + mf * 16 + g;
            if (row < M) {
                float2 o = make_float2(acc[mf][nf][0] + bi.x, acc[mf][nf][1] + bi.y);
                *(float2*)(C + (size_t)row * HC + col) = o;
            }
            if (row + 8 < M) {
                float2 o = make_float2(acc[mf][nf][2] + bi.x, acc[mf][nf][3] + bi.y);
                *(float2*)(C + (size_t)(row + 8) * HC + col) = o;
            }
        }
    }
}

// ---------------- fused score + softmax + aggregate --------------------------
// One block (128 threads = 4 warps) per dst node; warp h owns head h.
// Online softmax, 2-way unrolled edge loop to interleave SHFL chains.
__global__ void __launch_bounds__(128)
k_fused(const float* __restrict__ att_l, const float* __restrict__ bias_l,
        float* __restrict__ Hout) {
    int n = blockIdx.x;
    int t = threadIdx.x;
    int h = t >> 5, lane = t & 31;
    int b0 = g_rowptr[n], b1 = g_rowptr[n + 1];

    int o = h * 32 + lane;                    // float4 index into a 512-f row
    const float4* XL4 = (const float4*)g_XL;
    const float4* RR4 = (const float4*)g_REL;
    float4 xr = __ldg((const float4*)g_XR + (size_t)n * 128 + o);
    float4 aw = __ldg((const float4*)att_l + o);

    float m = -1e30f, den = 0.0f;
    float4 acc = make_float4(0.f, 0.f, 0.f, 0.f);

    int i = b0;
    for (; i + 2 <= b1; i += 2) {
        int s0 = g_esrc[i],     r0 = g_erel[i];
        int s1 = g_esrc[i + 1], r1 = g_erel[i + 1];
        float4 xl0 = __ldg(XL4 + (size_t)s0 * 128 + o);
        float4 rr0 = __ldg(RR4 + (size_t)r0 * 128 + o);
        float4 xl1 = __ldg(XL4 + (size_t)s1 * 128 + o);
        float4 rr1 = __ldg(RR4 + (size_t)r1 * 128 + o);

        float ax = xl0.x + xr.x + rr0.x; ax = ax > 0.f ? ax : 0.2f * ax;
        float ay = xl0.y + xr.y + rr0.y; ay = ay > 0.f ? ay : 0.2f * ay;
        float az = xl0.z + xr.z + rr0.z; az = az > 0.f ? az : 0.2f * az;
        float aw_ = xl0.w + xr.w + rr0.w; aw_ = aw_ > 0.f ? aw_ : 0.2f * aw_;
        float l0 = ax * aw.x + ay * aw.y + az * aw.z + aw_ * aw.w;

        float bx = xl1.x + xr.x + rr1.x; bx = bx > 0.f ? bx : 0.2f * bx;
        float by = xl1.y + xr.y + rr1.y; by = by > 0.f ? by : 0.2f * by;
        float bz = xl1.z + xr.z + rr1.z; bz = bz > 0.f ? bz : 0.2f * bz;
        float bw = xl1.w + xr.w + rr1.w; bw = bw > 0.f ? bw : 0.2f * bw;
        float l1 = bx * aw.x + by * aw.y + bz * aw.z + bw * aw.w;

#pragma unroll
        for (int off = 16; off; off >>= 1) {
            l0 += __shfl_xor_sync(0xFFFFFFFFu, l0, off);
            l1 += __shfl_xor_sync(0xFFFFFFFFu, l1, off);
        }

        float mn = fmaxf(m, fmaxf(l0, l1));
        float sc = __expf(m - mn);            // m=-1e30 first iter -> sc=0
        den *= sc;
        acc.x *= sc; acc.y *= sc; acc.z *= sc; acc.w *= sc;
        m = mn;
        float w0 = __expf(l0 - m);
        float w1 = __expf(l1 - m);
        den += w0 + w1;
        acc.x += w0 * xl0.x + w1 * xl1.x;
        acc.y += w0 * xl0.y + w1 * xl1.y;
        acc.z += w0 * xl0.z + w1 * xl1.z;
        acc.w += w0 * xl0.w + w1 * xl1.w;
    }
    if (i < b1) {
        int s0 = g_esrc[i], r0 = g_erel[i];
        float4 xl0 = __ldg(XL4 + (size_t)s0 * 128 + o);
        float4 rr0 = __ldg(RR4 + (size_t)r0 * 128 + o);
        float ax = xl0.x + xr.x + rr0.x; ax = ax > 0.f ? ax : 0.2f * ax;
        float ay = xl0.y + xr.y + rr0.y; ay = ay > 0.f ? ay : 0.2f * ay;
        float az = xl0.z + xr.z + rr0.z; az = az > 0.f ? az : 0.2f * az;
        float aw_ = xl0.w + xr.w + rr0.w; aw_ = aw_ > 0.f ? aw_ : 0.2f * aw_;
        float l0 = ax * aw.x + ay * aw.y + az * aw.z + aw_ * aw.w;
#pragma unroll
        for (int off = 16; off; off >>= 1)
            l0 += __shfl_xor_sync(0xFFFFFFFFu, l0, off);
        float mn = fmaxf(m, l0);
        float sc = __expf(m - mn);
        den *= sc;
        acc.x *= sc; acc.y *= sc; acc.z *= sc; acc.w *= sc;
        m = mn;
        float w0 = __expf(l0 - m);
        den += w0;
        acc.x += w0 * xl0.x; acc.y += w0 * xl0.y;
        acc.z += w0 * xl0.z; acc.w += w0 * xl0.w;
    }

    // head mean (0.25/den) + cross-head combine via smem
    __shared__ float sacc[NH][NF];
    float sc = 0.25f / den;
    sacc[h][lane * 4 + 0] = acc.x * sc;
    sacc[h][lane * 4 + 1] = acc.y * sc;
    sacc[h][lane * 4 + 2] = acc.z * sc;
    sacc[h][lane * 4 + 3] = acc.w * sc;
    __syncthreads();
    float out = sacc[0][t] + sacc[1][t] + sacc[2][t] + sacc[3][t]
              + __ldg(bias_l + t);
    Hout[(size_t)n * NF + t] = out;
}

// ---------------- launch ------------------------------------------------------
extern "C" void kernel_launch(void* const* d_in, const int* in_sizes, int n_in,
                              void* d_out, int out_size) {
    const float* x         = (const float*)d_in[0];
    const int*   ei        = (const int*)d_in[1];
    const float* relations = (const float*)d_in[2];
    const int*   relidx    = (const int*)d_in[3];
    const float* Wl        = (const float*)d_in[4];
    const float* bl        = (const float*)d_in[5];
    const float* Wr        = (const float*)d_in[6];
    const float* br        = (const float*)d_in[7];
    const float* We        = (const float*)d_in[8];
    const float* att       = (const float*)d_in[9];
    const float* bias      = (const float*)d_in[10];

    float *pXL, *pXR, *pREL, *pH;
    cudaGetSymbolAddress((void**)&pXL, g_XL);
    cudaGetSymbolAddress((void**)&pXR, g_XR);
    cudaGetSymbolAddress((void**)&pREL, g_REL);
    cudaGetSymbolAddress((void**)&pH, g_H);

    cudaFuncSetAttribute(gemm3_tf32,
                         cudaFuncAttributeMaxDynamicSharedMemorySize,
                         GEMM_SMEM_BYTES);
    // allow the driver to carve enough shared memory for 2 CTAs/SM
    cudaFuncSetAttribute(gemm3_tf32,
                         cudaFuncAttributePreferredSharedMemoryCarveout, 100);

    // ---- preprocessing (rebuilt every call: graph replay safe) ----
    k_init<<<(NR * NF + 255) / 256, 256>>>(relations, (float*)d_out, out_size);
    k_hist<<<(NE + 255) / 256, 256>>>(ei, relidx);
    k_scan<<<1, 1024>>>();
    k_eamean1<<<125, 128>>>(relations);
    k_eamean2<<<1, 128>>>();
    k_scatter<<<(NE + NN + 255) / 256, 256>>>(ei, relidx);

    dim3 grid3(4, (NN + 127) / 128, 3);     // z: XL, XR, REL

    const float* Hin = x;
    for (int l = 0; l < NL; l++) {
        gemm3_tf32<<<grid3, 256, GEMM_SMEM_BYTES>>>(
            Hin,
            Wl + (size_t)l * NF * HC, bl + (size_t)l * HC,
            Wr + (size_t)l * NF * HC, br + (size_t)l * HC,
            We + (size_t)l * NF * HC,
            pXL, pXR, pREL);

        float* Hout = (l == NL - 1) ? (float*)d_out
                                    : pH + (size_t)(l & 1) * NN * NF;
        k_fused<<<NN, 128>>>(att + (size_t)l * NH * NF,
                             bias + (size_t)l * NF, Hout);
        Hin = Hout;
    }
}

// round 10
// speedup vs baseline: 1.0825x; 1.0825x over previous
#include <cuda_runtime.h>
#include <cuda_bf16.h>
#include <math.h>

// Problem constants (fixed by the dataset)
#define NN   20000     // nodes
#define NE   100000    // edges (without self loops)
#define NR   1000      // relations
#define NF   128       // feature dim
#define NH   4         // heads
#define NL   4         // layers
#define HC   512       // NH*NF
#define ETOT (NE + NN) // edges incl self loops = 120000

// ---------------- scratch (static device globals; no runtime allocation) ----
__device__ float g_XL[(size_t)NN * HC];        // 41 MB  source projection
__device__ float g_XR[(size_t)NN * HC];        // 41 MB  target projection
__device__ float g_REL[(size_t)(NR + 1) * HC]; // 2 MB   edge embeddings (row NR = mean)
__device__ float g_relext[(size_t)(NR + 1) * NF]; // relations + mean row
__device__ float g_H[2 * (size_t)NN * NF];     // ping-pong node features
__device__ float g_part[125][NF];              // eamean partials
__device__ int   g_cnt[NN];
__device__ int   g_rcnt[NR];
__device__ int   g_rowptr[NN + 1];
__device__ int   g_offs[NN];
__device__ int   g_esrc[ETOT];
__device__ int   g_erel[ETOT];

// ---------------- preprocessing kernels -------------------------------------
// merged: reset histograms + copy relations into relext and output region
__global__ void k_init(const float* __restrict__ relations,
                       float* __restrict__ out, int out_size) {
    int i = blockIdx.x * blockDim.x + threadIdx.x;
    if (i < NN) g_cnt[i] = 1;              // self loop pre-counted
    if (i < NR) g_rcnt[i] = 0;
    if (i < NR * NF) {
        float v = relations[i];
        g_relext[i] = v;
        if (out_size >= NN * NF + NR * NF) out[NN * NF + i] = v;
    }
}

__global__ void k_hist(const int* __restrict__ ei, const int* __restrict__ relidx) {
    int e = blockIdx.x * blockDim.x + threadIdx.x;
    if (e < NE) {
        atomicAdd(&g_cnt[ei[NE + e]], 1);  // dst row
        atomicAdd(&g_rcnt[relidx[e]], 1);
    }
}

// single-block scan over 20000 counts -> rowptr + offs
__global__ void k_scan() {
    __shared__ int s[1024];
    int t = threadIdx.x;
    const int CH = 20;                      // 1024*20 >= 20000
    int beg = t * CH, end = min(beg + CH, NN);
    int sum = 0;
    for (int i = beg; i < end; i++) sum += g_cnt[i];
    s[t] = sum;
    __syncthreads();
    for (int off = 1; off < 1024; off <<= 1) {
        int v = (t >= off) ? s[t - off] : 0;
        __syncthreads();
        s[t] += v;
        __syncthreads();
    }
    int base = (t == 0) ? 0 : s[t - 1];
    for (int i = beg; i < end; i++) {
        g_rowptr[i] = base;
        g_offs[i]   = base;
        base += g_cnt[i];
    }
    if (t == 1023) g_rowptr[NN] = s[1023];
}

// eamean stage 1: 125 blocks x 128 threads, 8 relations each
__global__ void k_eamean1(const float* __restrict__ relations) {
    int b = blockIdx.x, f = threadIdx.x;
    float s = 0.0f;
#pragma unroll
    for (int j = 0; j < 8; j++) {
        int r = b * 8 + j;
        s += (float)g_rcnt[r] * __ldg(relations + (size_t)r * NF + f);
    }
    g_part[b][f] = s;
}

// eamean stage 2: combine 125 partials (deterministic)
__global__ void k_eamean2() {
    int f = threadIdx.x;
    float s = 0.0f;
#pragma unroll 5
    for (int b = 0; b < 125; b++) s += g_part[b][f];
    g_relext[(size_t)NR * NF + f] = s * (1.0f / NE);
}

// merged: scatter edges + self loops (counting-sort by dst)
__global__ void k_scatter(const int* __restrict__ ei, const int* __restrict__ relidx) {
    int e = blockIdx.x * blockDim.x + threadIdx.x;
    if (e < NE) {
        int s = ei[e], d = ei[NE + e];
        int pos = atomicAdd(&g_offs[d], 1);
        g_esrc[pos] = s;
        g_erel[pos] = relidx[e];
    } else if (e < NE + NN) {
        int n = e - NE;
        int pos = atomicAdd(&g_offs[n], 1);
        g_esrc[pos] = n;
        g_erel[pos] = NR;                   // mean-attr row
    }
}

// ---------------- tf32 tensor-core GEMM -------------------------------------
// One launch per layer: blockIdx.z selects {XL, XR, REL} problem.
// cp.async global->smem staging (no staging registers), double-buffered,
// tf32 convert at fragment load. 2 CTAs/SM target.
__device__ __forceinline__ unsigned f2tf(float x) {
    unsigned r;
    asm("cvt.rna.tf32.f32 %0, %1;" : "=r"(r) : "f"(x));
    return r;
}

__device__ __forceinline__ void mma_tf32(float* c, const unsigned* a,
                                         unsigned b0, unsigned b1) {
    asm("mma.sync.aligned.m16n8k8.row.col.f32.tf32.tf32.f32 "
        "{%0,%1,%2,%3},{%4,%5,%6,%7},{%8,%9},{%0,%1,%2,%3};"
        : "+f"(c[0]), "+f"(c[1]), "+f"(c[2]), "+f"(c[3])
        : "r"(a[0]), "r"(a[1]), "r"(a[2]), "r"(a[3]), "r"(b0), "r"(b1));
}

__device__ __forceinline__ void cp16(unsigned dst, const void* src, int n) {
    asm volatile("cp.async.cg.shared.global [%0], [%1], 16, %2;"
                 :: "r"(dst), "l"(src), "r"(n));
}
#define CP_COMMIT() asm volatile("cp.async.commit_group;" ::: "memory")
#define CP_WAIT0()  asm volatile("cp.async.wait_group 0;" ::: "memory")

#define AS_STRIDE 36                 // banks (4g+tg) distinct mod 32; 144B rows
#define BS_STRIDE 136                // banks (8tg+g) distinct mod 32; 544B rows
#define ASZ (128 * AS_STRIDE)        // floats per A buffer
#define BSZ (32 * BS_STRIDE)         // floats per B buffer
#define GEMM_SMEM_BYTES (2 * (ASZ + BSZ) * 4)   // 71680

__global__ void __launch_bounds__(256, 2)
gemm3_tf32(const float* __restrict__ Hin,
           const float* __restrict__ Wl, const float* __restrict__ bl,
           const float* __restrict__ Wr, const float* __restrict__ br,
           const float* __restrict__ We,
           float* __restrict__ XL, float* __restrict__ XR, float* __restrict__ REL) {
    const float* A; const float* B; const float* bias; float* C; int M;
    int z = blockIdx.z;
    if (z == 0)      { A = Hin;      B = Wl; bias = bl;      C = XL;  M = NN; }
    else if (z == 1) { A = Hin;      B = Wr; bias = br;      C = XR;  M = NN; }
    else             { A = g_relext; B = We; bias = nullptr; C = REL; M = NR + 1;
                       if (blockIdx.y * 128 >= NR + 1) return; }

    extern __shared__ float smemf[];
    float* Ab[2] = { smemf, smemf + ASZ };
    float* Bb[2] = { smemf + 2 * ASZ, smemf + 2 * ASZ + BSZ };
    unsigned Au[2] = { (unsigned)__cvta_generic_to_shared(Ab[0]),
                       (unsigned)__cvta_generic_to_shared(Ab[1]) };
    unsigned Bu[2] = { (unsigned)__cvta_generic_to_shared(Bb[0]),
                       (unsigned)__cvta_generic_to_shared(Bb[1]) };

    int t = threadIdx.x;
    int warp = t >> 5, lane = t & 31;
    int g = lane >> 2, tg = lane & 3;
    int m0 = blockIdx.y * 128, n0 = blockIdx.x * 128;
    int wm = (warp >> 1) * 32;       // 4 warps along M
    int wn = (warp & 1) * 64;        // 2 warps along N

    // async copy of one K-chunk (A: 128x32, B: 32x128) into buffer `buf`
    auto issue = [&](int kc, int buf) {
#pragma unroll
        for (int i = 0; i < 4; i++) {          // A: 1024 float4 / 256 thr
            int flat = i * 256 + t;
            int row = flat >> 3, c4 = flat & 7;
            int gr = m0 + row;
            int ok = (gr < M);
            const float4* src =
                (const float4*)(A + (size_t)(ok ? gr : 0) * NF + kc * 32) + c4;
            cp16(Au[buf] + (row * AS_STRIDE + c4 * 4) * 4, src, ok ? 16 : 0);
        }
#pragma unroll
        for (int i = 0; i < 4; i++) {          // B: 1024 float4 / 256 thr
            int flat = i * 256 + t;
            int kr = flat >> 5, c4 = flat & 31;
            const float4* src =
                (const float4*)(B + (size_t)(kc * 32 + kr) * HC + n0) + c4;
            cp16(Bu[buf] + (kr * BS_STRIDE + c4 * 4) * 4, src, 16);
        }
    };

    float acc[2][8][4] = {};

    issue(0, 0); CP_COMMIT();
    CP_WAIT0(); __syncthreads();

    for (int kc = 0; kc < 4; kc++) {
        if (kc < 3) { issue(kc + 1, (kc + 1) & 1); CP_COMMIT(); }

        const float* As = Ab[kc & 1];
        const float* Bs = Bb[kc & 1];
#pragma unroll
        for (int ks = 0; ks < 4; ks++) {
            int k0 = ks * 8;
            unsigned a[2][4];
#pragma unroll
            for (int mf = 0; mf < 2; mf++) {
                int r = wm + mf * 16 + g;
                a[mf][0] = f2tf(As[r * AS_STRIDE + k0 + tg]);
                a[mf][1] = f2tf(As[(r + 8) * AS_STRIDE + k0 + tg]);
                a[mf][2] = f2tf(As[r * AS_STRIDE + k0 + tg + 4]);
                a[mf][3] = f2tf(As[(r + 8) * AS_STRIDE + k0 + tg + 4]);
            }
#pragma unroll
            for (int nf = 0; nf < 8; nf++) {
                int c = wn + nf * 8 + g;
                unsigned b0 = f2tf(Bs[(k0 + tg) * BS_STRIDE + c]);
                unsigned b1 = f2tf(Bs[(k0 + tg + 4) * BS_STRIDE + c]);
                mma_tf32(acc[0][nf], a[0], b0, b1);
                mma_tf32(acc[1][nf], a[1], b0, b1);
            }
        }
        if (kc < 3) { CP_WAIT0(); __syncthreads(); }
    }

#pragma unroll
    for (int nf = 0; nf < 8; nf++) {
        int col = n0 + wn + nf * 8 + 2 * tg;
        float2 bi = make_float2(0.f, 0.f);
        if (bias) bi = *(const float2*)(bias + col);
#pragma unroll
        for (int mf = 0; mf < 2; mf++) {
            int row = m0 + wm + mf * 16 + g;
            if (row < M) {
                float2 o = make_float2(acc[mf][nf][0] + bi.x, acc[mf][nf][1] + bi.y);
                *(float2*)(C + (size_t)row * HC + col) = o;
            }
            if (row + 8 < M) {
                float2 o = make_float2(acc[mf][nf][2] + bi.x, acc[mf][nf][3] + bi.y);
                *(float2*)(C + (size_t)(row + 8) * HC + col) = o;
            }
        }
    }
}

// ---------------- fused score + softmax + aggregate --------------------------
// One block (128 threads = 4 warps) per dst node; warp h owns head h.
// Online softmax, 2-way unrolled edge loop to interleave SHFL chains.
__global__ void __launch_bounds__(128)
k_fused(const float* __restrict__ att_l, const float* __restrict__ bias_l,
        float* __restrict__ Hout) {
    int n = blockIdx.x;
    int t = threadIdx.x;
    int h = t >> 5, lane = t & 31;
    int b0 = g_rowptr[n], b1 = g_rowptr[n + 1];

    int o = h * 32 + lane;                    // float4 index into a 512-f row
    const float4* XL4 = (const float4*)g_XL;
    const float4* RR4 = (const float4*)g_REL;
    float4 xr = __ldg((const float4*)g_XR + (size_t)n * 128 + o);
    float4 aw = __ldg((const float4*)att_l + o);

    float m = -1e30f, den = 0.0f;
    float4 acc = make_float4(0.f, 0.f, 0.f, 0.f);

    int i = b0;
    for (; i + 2 <= b1; i += 2) {
        int s0 = g_esrc[i],     r0 = g_erel[i];
        int s1 = g_esrc[i + 1], r1 = g_erel[i + 1];
        float4 xl0 = __ldg(XL4 + (size_t)s0 * 128 + o);
        float4 rr0 = __ldg(RR4 + (size_t)r0 * 128 + o);
        float4 xl1 = __ldg(XL4 + (size_t)s1 * 128 + o);
        float4 rr1 = __ldg(RR4 + (size_t)r1 * 128 + o);

        float ax = xl0.x + xr.x + rr0.x; ax = ax > 0.f ? ax : 0.2f * ax;
        float ay = xl0.y + xr.y + rr0.y; ay = ay > 0.f ? ay : 0.2f * ay;
        float az = xl0.z + xr.z + rr0.z; az = az > 0.f ? az : 0.2f * az;
        float aw_ = xl0.w + xr.w + rr0.w; aw_ = aw_ > 0.f ? aw_ : 0.2f * aw_;
        float l0 = ax * aw.x + ay * aw.y + az * aw.z + aw_ * aw.w;

        float bx = xl1.x + xr.x + rr1.x; bx = bx > 0.f ? bx : 0.2f * bx;
        float by = xl1.y + xr.y + rr1.y; by = by > 0.f ? by : 0.2f * by;
        float bz = xl1.z + xr.z + rr1.z; bz = bz > 0.f ? bz : 0.2f * bz;
        float bw = xl1.w + xr.w + rr1.w; bw = bw > 0.f ? bw : 0.2f * bw;
        float l1 = bx * aw.x + by * aw.y + bz * aw.z + bw * aw.w;

#pragma unroll
        for (int off = 16; off; off >>= 1) {
            l0 += __shfl_xor_sync(0xFFFFFFFFu, l0, off);
            l1 += __shfl_xor_sync(0xFFFFFFFFu, l1, off);
        }

        float mn = fmaxf(m, fmaxf(l0, l1));
        float sc = __expf(m - mn);            // m=-1e30 first iter -> sc=0
        den *= sc;
        acc.x *= sc; acc.y *= sc; acc.z *= sc; acc.w *= sc;
        m = mn;
        float w0 = __expf(l0 - m);
        float w1 = __expf(l1 - m);
        den += w0 + w1;
        acc.x += w0 * xl0.x + w1 * xl1.x;
        acc.y += w0 * xl0.y + w1 * xl1.y;
        acc.z += w0 * xl0.z + w1 * xl1.z;
        acc.w += w0 * xl0.w + w1 * xl1.w;
    }
    if (i < b1) {
        int s0 = g_esrc[i], r0 = g_erel[i];
        float4 xl0 = __ldg(XL4 + (size_t)s0 * 128 + o);
        float4 rr0 = __ldg(RR4 + (size_t)r0 * 128 + o);
        float ax = xl0.x + xr.x + rr0.x; ax = ax > 0.f ? ax : 0.2f * ax;
        float ay = xl0.y + xr.y + rr0.y; ay = ay > 0.f ? ay : 0.2f * ay;
        float az = xl0.z + xr.z + rr0.z; az = az > 0.f ? az : 0.2f * az;
        float aw_ = xl0.w + xr.w + rr0.w; aw_ = aw_ > 0.f ? aw_ : 0.2f * aw_;
        float l0 = ax * aw.x + ay * aw.y + az * aw.z + aw_ * aw.w;
#pragma unroll
        for (int off = 16; off; off >>= 1)
            l0 += __shfl_xor_sync(0xFFFFFFFFu, l0, off);
        float mn = fmaxf(m, l0);
        float sc = __expf(m - mn);
        den *= sc;
        acc.x *= sc; acc.y *= sc; acc.z *= sc; acc.w *= sc;
        m = mn;
        float w0 = __expf(l0 - m);
        den += w0;
        acc.x += w0 * xl0.x; acc.y += w0 * xl0.y;
        acc.z += w0 * xl0.z; acc.w += w0 * xl0.w;
    }

    // head mean (0.25/den) + cross-head combine via smem
    __shared__ float sacc[NH][NF];
    float sc = 0.25f / den;
    sacc[h][lane * 4 + 0] = acc.x * sc;
    sacc[h][lane * 4 + 1] = acc.y * sc;
    sacc[h][lane * 4 + 2] = acc.z * sc;
    sacc[h][lane * 4 + 3] = acc.w * sc;
    __syncthreads();
    float out = sacc[0][t] + sacc[1][t] + sacc[2][t] + sacc[3][t]
              + __ldg(bias_l + t);
    Hout[(size_t)n * NF + t] = out;
}

// ---------------- launch ------------------------------------------------------
extern "C" void kernel_launch(void* const* d_in, const int* in_sizes, int n_in,
                              void* d_out, int out_size) {
    const float* x         = (const float*)d_in[0];
    const int*   ei        = (const int*)d_in[1];
    const float* relations = (const float*)d_in[2];
    const int*   relidx    = (const int*)d_in[3];
    const float* Wl        = (const float*)d_in[4];
    const float* bl        = (const float*)d_in[5];
    const float* Wr        = (const float*)d_in[6];
    const float* br        = (const float*)d_in[7];
    const float* We        = (const float*)d_in[8];
    const float* att       = (const float*)d_in[9];
    const float* bias      = (const float*)d_in[10];

    float *pXL, *pXR, *pREL, *pH;
    cudaGetSymbolAddress((void**)&pXL, g_XL);
    cudaGetSymbolAddress((void**)&pXR, g_XR);
    cudaGetSymbolAddress((void**)&pREL, g_REL);
    cudaGetSymbolAddress((void**)&pH, g_H);

    cudaFuncSetAttribute(gemm3_tf32,
                         cudaFuncAttributeMaxDynamicSharedMemorySize,
                         GEMM_SMEM_BYTES);

    // ---- preprocessing (rebuilt every call: graph replay safe) ----
    k_init<<<(NR * NF + 255) / 256, 256>>>(relations, (float*)d_out, out_size);
    k_hist<<<(NE + 255) / 256, 256>>>(ei, relidx);
    k_scan<<<1, 1024>>>();
    k_eamean1<<<125, 128>>>(relations);
    k_eamean2<<<1, 128>>>();
    k_scatter<<<(NE + NN + 255) / 256, 256>>>(ei, relidx);

    dim3 grid3(4, (NN + 127) / 128, 3);     // z: XL, XR, REL

    const float* Hin = x;
    for (int l = 0; l < NL; l++) {
        gemm3_tf32<<<grid3, 256, GEMM_SMEM_BYTES>>>(
            Hin,
            Wl + (size_t)l * NF * HC, bl + (size_t)l * HC,
            Wr + (size_t)l * NF * HC, br + (size_t)l * HC,
            We + (size_t)l * NF * HC,
            pXL, pXR, pREL);

        float* Hout = (l == NL - 1) ? (float*)d_out
                                    : pH + (size_t)(l & 1) * NN * NF;
        k_fused<<<NN, 128>>>(att + (size_t)l * NH * NF,
                             bias + (size_t)l * NF, Hout);
        Hin = Hout;
    }
}